// round 1
// baseline (speedup 1.0000x reference)
#include <cuda_runtime.h>

#define H   64
#define G   256   // 4*H
#define F   5
#define BS  8     // samples per block
#define TPB 256   // one thread per gate row
#define RB  128   // rank-loss reduce blocks

__device__ float g_rank_part[RB];
__device__ float g_reg_part[2];   // [0] = sum (pred-ret)^2*m, [1] = sum m

__device__ __forceinline__ float sigf(float x) {
    // 1/(1+e^-x); saturates cleanly at 0/1 for large |x|
    return __fdividef(1.f, 1.f + __expf(-x));
}
__device__ __forceinline__ float tanhf_fast(float x) {
    // 1 - 2/(e^{2x}+1); e->inf => 1, e->0 => -1, no inf/inf NaN
    float e = __expf(2.f * x);
    return 1.f - __fdividef(2.f, e + 1.f);
}

__global__ __launch_bounds__(TPB, 2)
void lstm_kernel(const float* __restrict__ feature,
                 const float* __restrict__ Wih, const float* __restrict__ Whh,
                 const float* __restrict__ bih, const float* __restrict__ bhh,
                 const float* __restrict__ Wd,  const float* __restrict__ bd,
                 float* __restrict__ pred, int N, int T)
{
    const int r  = threadIdx.x;          // gate row 0..255 (i,f,g,o blocks of 64)
    const int n0 = blockIdx.x * BS;

    // Per-thread resident weights
    float wh[H];
#pragma unroll
    for (int k = 0; k < H; k++) wh[k] = Whh[r * H + k];
    float wi[F];
#pragma unroll
    for (int f = 0; f < F; f++) wi[f] = Wih[r * F + f];
    const float bias = bih[r] + bhh[r];

    __shared__ float h_sm[BS][H];        // current hidden state
    __shared__ float g_sm[BS][G];        // gate pre-activations
    __shared__ float x_sm[2][BS][F];     // double-buffered input features

    float c_reg[BS * H / TPB];           // cell state (updater threads)
#pragma unroll
    for (int u = 0; u < BS * H / TPB; u++) {
        c_reg[u] = 0.f;
        int idx = r + TPB * u;
        h_sm[idx >> 6][idx & 63] = 0.f;
    }
    // zero-init x buffers (out-of-range samples read zeros, results discarded)
    if (r < BS * F) { int s = r / F, f = r % F; x_sm[0][s][f] = 0.f; x_sm[1][s][f] = 0.f; }
    __syncthreads();
    if (r < BS * F) {
        int s = r / F, f = r % F;
        if (n0 + s < N) x_sm[0][s][f] = feature[(size_t)(n0 + s) * T * F + f];
    }
    __syncthreads();

    for (int t = 0; t < T; t++) {
        const int buf = t & 1;

        // ---- phase 1: gate = bias + Whh_row . h  (+ Wih_row . x last, hides x load)
        float acc[BS];
#pragma unroll
        for (int s = 0; s < BS; s++) acc[s] = bias;
#pragma unroll
        for (int s = 0; s < BS; s++) {
            const float4* h4 = (const float4*)h_sm[s];   // broadcast reads, conflict-free
#pragma unroll
            for (int k4 = 0; k4 < H / 4; k4++) {
                float4 hv = h4[k4];
                acc[s] += wh[4 * k4 + 0] * hv.x;
                acc[s] += wh[4 * k4 + 1] * hv.y;
                acc[s] += wh[4 * k4 + 2] * hv.z;
                acc[s] += wh[4 * k4 + 3] * hv.w;
            }
        }
#pragma unroll
        for (int s = 0; s < BS; s++) {
            float a = acc[s];
#pragma unroll
            for (int f = 0; f < F; f++) a += wi[f] * x_sm[buf][s][f];
            g_sm[s][r] = a;
        }
        __syncthreads();

        // ---- prefetch x for t+1 into the other buffer (consumed after next sync)
        if (t + 1 < T && r < BS * F) {
            int s = r / F, f = r % F;
            if (n0 + s < N)
                x_sm[buf ^ 1][s][f] =
                    feature[(size_t)(n0 + s) * T * F + (size_t)(t + 1) * F + f];
        }

        // ---- phase 2: elementwise LSTM cell update (PyTorch gate order i,f,g,o)
#pragma unroll
        for (int u = 0; u < BS * H / TPB; u++) {
            int idx = r + TPB * u;
            int s = idx >> 6, j = idx & 63;
            float ig = sigf(g_sm[s][j]);
            float fg = sigf(g_sm[s][H + j]);
            float gg = tanhf_fast(g_sm[s][2 * H + j]);
            float og = sigf(g_sm[s][3 * H + j]);
            float c  = fg * c_reg[u] + ig * gg;
            c_reg[u] = c;
            h_sm[s][j] = og * tanhf_fast(c);
        }
        __syncthreads();
    }

    // ---- head: warp w -> sample w; pred = leaky_relu(h . Wd + bd, 0.2)
    int w = r >> 5, lane = r & 31;
    if (w < BS && n0 + w < N) {
        float p = h_sm[w][lane] * Wd[lane] + h_sm[w][lane + 32] * Wd[lane + 32];
#pragma unroll
        for (int off = 16; off; off >>= 1) p += __shfl_down_sync(0xffffffffu, p, off);
        if (lane == 0) {
            p += bd[0];
            p = p > 0.f ? p : 0.2f * p;
            pred[n0 + w] = p;
        }
    }
}

// Pairwise rank loss partials + masked MSE partials (deterministic, no atomics).
__global__ void pair_kernel(const float* __restrict__ pred, const float* __restrict__ ret,
                            const unsigned* __restrict__ mask, int N)
{
    __shared__ float p_sm[4096];
    __shared__ float t_sm[4096];
    __shared__ unsigned char m_sm[4096];
    __shared__ float red[256];
    const int tid = threadIdx.x;

    for (int n = tid; n < N; n += blockDim.x) {
        p_sm[n] = pred[n];
        t_sm[n] = ret[n];
        m_sm[n] = (mask[n] != 0u) ? 1 : 0;   // works for int32 and float32 masks
    }
    __syncthreads();

    float rsum = 0.f;
    for (int i = blockIdx.x; i < N; i += gridDim.x) {
        if (!m_sm[i]) continue;              // uniform per block
        float pi = p_sm[i], gi = t_sm[i];
        for (int j = tid; j < N; j += blockDim.x) {
            float v = -(p_sm[j] - pi) * (t_sm[j] - gi);
            v = fmaxf(v, 0.f);
            rsum += v * (float)m_sm[j];
        }
    }
    red[tid] = rsum;
    __syncthreads();
    for (int s = 128; s; s >>= 1) { if (tid < s) red[tid] += red[tid + s]; __syncthreads(); }
    if (tid == 0) g_rank_part[blockIdx.x] = red[0];

    if (blockIdx.x == 0) {
        float ssq = 0.f, sm = 0.f;
        for (int n = tid; n < N; n += blockDim.x) {
            float m = (float)m_sm[n];
            float d = p_sm[n] - t_sm[n];
            ssq += d * d * m;
            sm  += m;
        }
        __syncthreads();
        red[tid] = ssq; __syncthreads();
        for (int s = 128; s; s >>= 1) { if (tid < s) red[tid] += red[tid + s]; __syncthreads(); }
        if (tid == 0) g_reg_part[0] = red[0];
        __syncthreads();
        red[tid] = sm; __syncthreads();
        for (int s = 128; s; s >>= 1) { if (tid < s) red[tid] += red[tid + s]; __syncthreads(); }
        if (tid == 0) g_reg_part[1] = red[0];
    }
}

__global__ void finalize_kernel(float* __restrict__ out, int N)
{
    if (threadIdx.x == 0 && blockIdx.x == 0) {
        float srank = 0.f;
        for (int b = 0; b < RB; b++) srank += g_rank_part[b];
        float reg  = g_reg_part[0] / (g_reg_part[1] + 1e-8f);
        float rank = srank / ((float)N * (float)N);
        out[N]     = reg + rank;   // loss
        out[N + 1] = reg;          // reg_loss
        out[N + 2] = rank;         // rank_loss
    }
}

extern "C" void kernel_launch(void* const* d_in, const int* in_sizes, int n_in,
                              void* d_out, int out_size)
{
    const float*    feature = (const float*)d_in[0];
    const float*    ret     = (const float*)d_in[1];
    const unsigned* mask    = (const unsigned*)d_in[2];
    const float*    Wih     = (const float*)d_in[3];
    const float*    Whh     = (const float*)d_in[4];
    const float*    bih     = (const float*)d_in[5];
    const float*    bhh     = (const float*)d_in[6];
    const float*    Wd      = (const float*)d_in[7];
    const float*    bd      = (const float*)d_in[8];
    float* out = (float*)d_out;

    const int N = in_sizes[1];                 // 4096
    const int T = in_sizes[0] / (N * F);       // 512

    const int grid = (N + BS - 1) / BS;
    lstm_kernel<<<grid, TPB>>>(feature, Wih, Whh, bih, bhh, Wd, bd, out, N, T);
    pair_kernel<<<RB, 256>>>(out, ret, mask, N);
    finalize_kernel<<<1, 32>>>(out, N);
}

// round 2
// speedup vs baseline: 1.0402x; 1.0402x over previous
#include <cuda_runtime.h>

#define H   64
#define G   256   // 4*H
#define F   5
#define BS  8     // samples per block
#define TPB 256   // one thread per gate row
#define RB  128   // rank-loss reduce blocks

__device__ float g_rank_part[RB];
__device__ float g_reg_part[2];

__device__ __forceinline__ float sigf(float x) {
    return __fdividef(1.f, 1.f + __expf(-x));
}
__device__ __forceinline__ float tanhf_fast(float x) {
    float e = __expf(2.f * x);
    return 1.f - __fdividef(2.f, e + 1.f);
}

// packed dual-FMA: per-lane fma.rn on two f32s in one issue slot (sm_103a FFMA2)
__device__ __forceinline__ unsigned long long fma2(unsigned long long a,
                                                   unsigned long long b,
                                                   unsigned long long c) {
    unsigned long long d;
    asm("fma.rn.f32x2 %0, %1, %2, %3;" : "=l"(d) : "l"(a), "l"(b), "l"(c));
    return d;
}

__global__ __launch_bounds__(TPB, 2)
void lstm_kernel(const float* __restrict__ feature,
                 const float* __restrict__ Wih, const float* __restrict__ Whh,
                 const float* __restrict__ bih, const float* __restrict__ bhh,
                 const float* __restrict__ Wd,  const float* __restrict__ bd,
                 float* __restrict__ pred, int N, int T)
{
    const int r  = threadIdx.x;          // gate row 0..255 (i,f,g,o blocks of 64)
    const int n0 = blockIdx.x * BS;

    // Per-thread resident weights, k-packed as f32x2 pairs (64 regs total)
    unsigned long long wh2[H / 2];
    {
        const ulonglong2* w4 = (const ulonglong2*)(Whh + r * H);  // rows are 256B, 16B-aligned
#pragma unroll
        for (int q = 0; q < H / 4; q++) {
            ulonglong2 v = w4[q];
            wh2[2 * q + 0] = v.x;
            wh2[2 * q + 1] = v.y;
        }
    }
    float wi[F];
#pragma unroll
    for (int f = 0; f < F; f++) wi[f] = Wih[r * F + f];
    const float bias = bih[r] + bhh[r];

    __shared__ __align__(16) float h_sm[BS][H];   // current hidden state
    __shared__ float g_sm[BS][G];                 // gate pre-activations
    __shared__ float x_sm[2][BS][F];              // double-buffered features

    float c_reg[BS * H / TPB];
#pragma unroll
    for (int u = 0; u < BS * H / TPB; u++) {
        c_reg[u] = 0.f;
        int idx = r + TPB * u;
        h_sm[idx >> 6][idx & 63] = 0.f;
    }
    if (r < BS * F) { int s = r / F, f = r % F; x_sm[0][s][f] = 0.f; x_sm[1][s][f] = 0.f; }
    __syncthreads();
    if (r < BS * F) {
        int s = r / F, f = r % F;
        if (n0 + s < N) x_sm[0][s][f] = feature[(size_t)(n0 + s) * T * F + f];
    }
    __syncthreads();

    for (int t = 0; t < T; t++) {
        const int buf = t & 1;

        // ---- phase 1: gate = bias + Whh_row . h + Wih_row . x
        // k-packed f32x2: one LDS.128 feeds two FFMA2 (4 scalar FMAs)
#pragma unroll
        for (int s = 0; s < BS; s++) {
            unsigned long long acc = 0ULL;
            const ulonglong2* h2 = (const ulonglong2*)h_sm[s];  // uniform -> broadcast
#pragma unroll
            for (int q = 0; q < H / 4; q++) {
                ulonglong2 hv = h2[q];
                acc = fma2(wh2[2 * q + 0], hv.x, acc);
                acc = fma2(wh2[2 * q + 1], hv.y, acc);
            }
            float lo = __uint_as_float((unsigned)(acc & 0xffffffffULL));
            float hi = __uint_as_float((unsigned)(acc >> 32));
            float a = lo + hi + bias;
#pragma unroll
            for (int f = 0; f < F; f++) a = fmaf(wi[f], x_sm[buf][s][f], a);
            g_sm[s][r] = a;
        }
        __syncthreads();

        // ---- prefetch x for t+1 (consumed after next sync)
        if (t + 1 < T && r < BS * F) {
            int s = r / F, f = r % F;
            if (n0 + s < N)
                x_sm[buf ^ 1][s][f] =
                    feature[(size_t)(n0 + s) * T * F + (size_t)(t + 1) * F + f];
        }

        // ---- phase 2: elementwise LSTM cell (PyTorch gate order i,f,g,o)
#pragma unroll
        for (int u = 0; u < BS * H / TPB; u++) {
            int idx = r + TPB * u;
            int s = idx >> 6, j = idx & 63;
            float ig = sigf(g_sm[s][j]);
            float fg = sigf(g_sm[s][H + j]);
            float gg = tanhf_fast(g_sm[s][2 * H + j]);
            float og = sigf(g_sm[s][3 * H + j]);
            float c  = fg * c_reg[u] + ig * gg;
            c_reg[u] = c;
            h_sm[s][j] = og * tanhf_fast(c);
        }
        __syncthreads();
    }

    // ---- head: warp w -> sample w; pred = leaky_relu(h . Wd + bd, 0.2)
    int w = r >> 5, lane = r & 31;
    if (w < BS && n0 + w < N) {
        float p = h_sm[w][lane] * Wd[lane] + h_sm[w][lane + 32] * Wd[lane + 32];
#pragma unroll
        for (int off = 16; off; off >>= 1) p += __shfl_down_sync(0xffffffffu, p, off);
        if (lane == 0) {
            p += bd[0];
            p = p > 0.f ? p : 0.2f * p;
            pred[n0 + w] = p;
        }
    }
}

// Pairwise rank loss partials + masked MSE partials (deterministic, no atomics).
__global__ void pair_kernel(const float* __restrict__ pred, const float* __restrict__ ret,
                            const unsigned* __restrict__ mask, int N)
{
    __shared__ float p_sm[4096];
    __shared__ float t_sm[4096];
    __shared__ unsigned char m_sm[4096];
    __shared__ float red[256];
    const int tid = threadIdx.x;

    for (int n = tid; n < N; n += blockDim.x) {
        p_sm[n] = pred[n];
        t_sm[n] = ret[n];
        m_sm[n] = (mask[n] != 0u) ? 1 : 0;
    }
    __syncthreads();

    float rsum = 0.f;
    for (int i = blockIdx.x; i < N; i += gridDim.x) {
        if (!m_sm[i]) continue;
        float pi = p_sm[i], gi = t_sm[i];
        for (int j = tid; j < N; j += blockDim.x) {
            float v = -(p_sm[j] - pi) * (t_sm[j] - gi);
            v = fmaxf(v, 0.f);
            rsum += v * (float)m_sm[j];
        }
    }
    red[tid] = rsum;
    __syncthreads();
    for (int s = 128; s; s >>= 1) { if (tid < s) red[tid] += red[tid + s]; __syncthreads(); }
    if (tid == 0) g_rank_part[blockIdx.x] = red[0];

    if (blockIdx.x == 0) {
        float ssq = 0.f, sm = 0.f;
        for (int n = tid; n < N; n += blockDim.x) {
            float m = (float)m_sm[n];
            float d = p_sm[n] - t_sm[n];
            ssq += d * d * m;
            sm  += m;
        }
        __syncthreads();
        red[tid] = ssq; __syncthreads();
        for (int s = 128; s; s >>= 1) { if (tid < s) red[tid] += red[tid + s]; __syncthreads(); }
        if (tid == 0) g_reg_part[0] = red[0];
        __syncthreads();
        red[tid] = sm; __syncthreads();
        for (int s = 128; s; s >>= 1) { if (tid < s) red[tid] += red[tid + s]; __syncthreads(); }
        if (tid == 0) g_reg_part[1] = red[0];
    }
}

__global__ void finalize_kernel(float* __restrict__ out, int N)
{
    if (threadIdx.x == 0 && blockIdx.x == 0) {
        float srank = 0.f;
        for (int b = 0; b < RB; b++) srank += g_rank_part[b];
        float reg  = g_reg_part[0] / (g_reg_part[1] + 1e-8f);
        float rank = srank / ((float)N * (float)N);
        out[N]     = reg + rank;
        out[N + 1] = reg;
        out[N + 2] = rank;
    }
}

extern "C" void kernel_launch(void* const* d_in, const int* in_sizes, int n_in,
                              void* d_out, int out_size)
{
    const float*    feature = (const float*)d_in[0];
    const float*    ret     = (const float*)d_in[1];
    const unsigned* mask    = (const unsigned*)d_in[2];
    const float*    Wih     = (const float*)d_in[3];
    const float*    Whh     = (const float*)d_in[4];
    const float*    bih     = (const float*)d_in[5];
    const float*    bhh     = (const float*)d_in[6];
    const float*    Wd      = (const float*)d_in[7];
    const float*    bd      = (const float*)d_in[8];
    float* out = (float*)d_out;

    const int N = in_sizes[1];                 // 4096
    const int T = in_sizes[0] / (N * F);       // 512

    const int grid = (N + BS - 1) / BS;
    lstm_kernel<<<grid, TPB>>>(feature, Wih, Whh, bih, bhh, Wd, bd, out, N, T);
    pair_kernel<<<RB, 256>>>(out, ret, mask, N);
    finalize_kernel<<<1, 32>>>(out, N);
}